// round 1
// baseline (speedup 1.0000x reference)
#include <cuda_runtime.h>
#include <math.h>

#define B_ 64
#define T_ 512
#define H_ 1024
#define E_ 512
#define V_ 32000
#define M_BT (B_ * T_)        // 32768

// ---------------- scratch (device globals; no allocation allowed) ----------------
__device__ float g_rnn_in[B_ * (E_ + H_)];      // [64, 1536]  = [emb | context]
__device__ float g_bias_a[B_ * H_];             // attn_b + h @ W1^T
__device__ float g_scores_part[8 * M_BT];       // per-n-tile partial scores
__device__ float g_gi[B_ * 3 * H_];
__device__ float g_gh[B_ * 3 * H_];
__device__ float g_cat2[B_ * 2 * H_];           // [h_new | context]

// ---------------- K0: embedding gather ----------------
__global__ void gather_emb_k(const int* __restrict__ x,
                             const float* __restrict__ embW,
                             float* __restrict__ rnn_in) {
    int b = blockIdx.x;
    int row = x[b];
    for (int e = threadIdx.x; e < E_; e += blockDim.x)
        rnn_in[b * (E_ + H_) + e] = embW[row * E_ + e];
}

// ---------------- generic M=64 GEMM: C[64,N] = A[64,K] @ W[N,K]^T + bias ----------------
// grid.x = N/64, block = 256 threads, 4x4 micro-tile, BK=16
__global__ void gemm_m64_k(const float* __restrict__ A, int lda,
                           const float* __restrict__ W, int ldw,
                           const float* __restrict__ bias,
                           float* __restrict__ C, int ldc, int K) {
    __shared__ float As[16][64];
    __shared__ float Ws[16][64];
    const int tid = threadIdx.x;
    const int n0 = blockIdx.x * 64;
    const int lrow = tid >> 2;          // 0..63
    const int kq = (tid & 3) * 4;       // 0,4,8,12
    const int ty = tid >> 4;            // 0..15 (m groups of 4)
    const int tx = tid & 15;            // 0..15 (n groups of 4)

    float acc[4][4] = {};

    for (int kk = 0; kk < K; kk += 16) {
        float4 av = *(const float4*)&A[lrow * lda + kk + kq];
        float4 wv = *(const float4*)&W[(size_t)(n0 + lrow) * ldw + kk + kq];
        __syncthreads();
        As[kq + 0][lrow] = av.x; As[kq + 1][lrow] = av.y;
        As[kq + 2][lrow] = av.z; As[kq + 3][lrow] = av.w;
        Ws[kq + 0][lrow] = wv.x; Ws[kq + 1][lrow] = wv.y;
        Ws[kq + 2][lrow] = wv.z; Ws[kq + 3][lrow] = wv.w;
        __syncthreads();
        #pragma unroll
        for (int k = 0; k < 16; k++) {
            float4 a = *(const float4*)&As[k][ty * 4];
            float4 w = *(const float4*)&Ws[k][tx * 4];
            float af[4] = {a.x, a.y, a.z, a.w};
            float wf[4] = {w.x, w.y, w.z, w.w};
            #pragma unroll
            for (int i = 0; i < 4; i++)
                #pragma unroll
                for (int j = 0; j < 4; j++)
                    acc[i][j] = fmaf(af[i], wf[j], acc[i][j]);
        }
    }
    #pragma unroll
    for (int i = 0; i < 4; i++) {
        int m = ty * 4 + i;
        #pragma unroll
        for (int j = 0; j < 4; j++) {
            int n = n0 + tx * 4 + j;
            C[(size_t)m * ldc + n] = acc[i][j] + bias[n];
        }
    }
}

// ---------------- K2: fused energy GEMM + relu*v reduction ----------------
// C[m,h] = sum_k enc[m,k] * attn_W[h, 1024+k],   m = t*64 + b
// scores_part[nTile, m] = sum_{h in tile} relu(C + bias_a[b,h]) * v[h]
// grid = (8, 256), block = 256, 128x128x16 tiles, 8x8 micro
__global__ void attn_energy_k(const float* __restrict__ enc,
                              const float* __restrict__ attnW,
                              const float* __restrict__ bias_a,
                              const float* __restrict__ v,
                              float* __restrict__ scores_part) {
    __shared__ float As[16][128];
    __shared__ float Ws[16][128];
    __shared__ float red[128 * 16];

    const int tid = threadIdx.x;
    const int m0 = blockIdx.y * 128;
    const int n0 = blockIdx.x * 128;
    const int ty = tid >> 4;     // 0..15
    const int tx = tid & 15;     // 0..15

    float acc[8][8] = {};

    for (int kk = 0; kk < H_; kk += 16) {
        __syncthreads();
        #pragma unroll
        for (int i = 0; i < 2; i++) {
            int idx = tid + i * 256;
            int row = idx >> 2;
            int kq = (idx & 3) * 4;
            float4 av = *(const float4*)&enc[(size_t)(m0 + row) * H_ + kk + kq];
            As[kq + 0][row] = av.x; As[kq + 1][row] = av.y;
            As[kq + 2][row] = av.z; As[kq + 3][row] = av.w;
            float4 wv = *(const float4*)&attnW[(size_t)(n0 + row) * (2 * H_) + H_ + kk + kq];
            Ws[kq + 0][row] = wv.x; Ws[kq + 1][row] = wv.y;
            Ws[kq + 2][row] = wv.z; Ws[kq + 3][row] = wv.w;
        }
        __syncthreads();
        #pragma unroll
        for (int k = 0; k < 16; k++) {
            float a[8], w[8];
            *(float4*)&a[0] = *(const float4*)&As[k][ty * 8];
            *(float4*)&a[4] = *(const float4*)&As[k][ty * 8 + 4];
            *(float4*)&w[0] = *(const float4*)&Ws[k][tx * 8];
            *(float4*)&w[4] = *(const float4*)&Ws[k][tx * 8 + 4];
            #pragma unroll
            for (int i = 0; i < 8; i++)
                #pragma unroll
                for (int j = 0; j < 8; j++)
                    acc[i][j] = fmaf(a[i], w[j], acc[i][j]);
        }
    }

    // epilogue: +bias_a, relu, *v, row-reduce over the 128 h columns of this tile
    float rowsum[8];
    #pragma unroll
    for (int i = 0; i < 8; i++) {
        int m = m0 + ty * 8 + i;
        int b = m & (B_ - 1);            // m = t*64 + b
        float s = 0.f;
        #pragma unroll
        for (int j = 0; j < 8; j++) {
            int h = n0 + tx * 8 + j;
            float val = acc[i][j] + bias_a[b * H_ + h];
            s += fmaxf(val, 0.f) * v[h];
        }
        rowsum[i] = s;
    }
    __syncthreads();
    #pragma unroll
    for (int i = 0; i < 8; i++)
        red[(ty * 8 + i) * 16 + tx] = rowsum[i];
    __syncthreads();
    if (tid < 128) {
        float s = 0.f;
        #pragma unroll
        for (int x = 0; x < 16; x++) s += red[tid * 16 + x];
        scores_part[blockIdx.x * M_BT + m0 + tid] = s;
    }
}

// ---------------- K3: softmax over T, writes attn_w output ----------------
__global__ void softmax_k(const float* __restrict__ scores_part,
                          float* __restrict__ attn_w_out) {
    int b = blockIdx.x;
    int t = threadIdx.x;
    __shared__ float sh[512];
    float s = 0.f;
    #pragma unroll
    for (int p = 0; p < 8; p++) s += scores_part[p * M_BT + t * B_ + b];
    sh[t] = s;
    __syncthreads();
    for (int off = 256; off > 0; off >>= 1) {
        if (t < off) sh[t] = fmaxf(sh[t], sh[t + off]);
        __syncthreads();
    }
    float mx = sh[0];
    __syncthreads();
    float e = expf(s - mx);
    sh[t] = e;
    __syncthreads();
    for (int off = 256; off > 0; off >>= 1) {
        if (t < off) sh[t] += sh[t + off];
        __syncthreads();
    }
    attn_w_out[b * T_ + t] = e / sh[0];
}

// ---------------- K4: context = attn_w @ enc; also fills rnn_in and cat2 tails ----------------
__global__ void context_k(const float* __restrict__ enc,
                          const float* __restrict__ attn_w,
                          float* __restrict__ rnn_in,
                          float* __restrict__ cat2) {
    int b = blockIdx.y;
    int h = blockIdx.x * 128 + threadIdx.x;
    __shared__ float w[T_];
    for (int t = threadIdx.x; t < T_; t += 128) w[t] = attn_w[b * T_ + t];
    __syncthreads();
    float acc = 0.f;
    #pragma unroll 4
    for (int t = 0; t < T_; t++)
        acc = fmaf(w[t], enc[(size_t)(t * B_ + b) * H_ + h], acc);
    rnn_in[b * (E_ + H_) + E_ + h] = acc;
    cat2[b * (2 * H_) + H_ + h] = acc;
}

// ---------------- K6: GRU gates ----------------
__global__ void gates_k(const float* __restrict__ gi,
                        const float* __restrict__ gh,
                        const float* __restrict__ lh,
                        float* __restrict__ hnew_out,
                        float* __restrict__ cat2) {
    int b = blockIdx.x;
    for (int h = threadIdx.x; h < H_; h += blockDim.x) {
        float r = 1.f / (1.f + expf(-(gi[b * 3 * H_ + h] + gh[b * 3 * H_ + h])));
        float z = 1.f / (1.f + expf(-(gi[b * 3 * H_ + H_ + h] + gh[b * 3 * H_ + H_ + h])));
        float n = tanhf(gi[b * 3 * H_ + 2 * H_ + h] + r * gh[b * 3 * H_ + 2 * H_ + h]);
        float hp = lh[b * H_ + h];
        float hn = (1.f - z) * n + z * hp;
        hnew_out[b * H_ + h] = hn;
        cat2[b * (2 * H_) + h] = hn;
    }
}

// ---------------- K8: in-place log_softmax on logits rows ----------------
__global__ void logsoftmax_k(float* __restrict__ logits) {
    int b = blockIdx.x;
    int tid = threadIdx.x;
    __shared__ float sh[1024];
    float* row = logits + (size_t)b * V_;
    float mx = -1e30f;
    for (int n = tid; n < V_; n += 1024) mx = fmaxf(mx, row[n]);
    sh[tid] = mx;
    __syncthreads();
    for (int off = 512; off > 0; off >>= 1) {
        if (tid < off) sh[tid] = fmaxf(sh[tid], sh[tid + off]);
        __syncthreads();
    }
    mx = sh[0];
    __syncthreads();
    float sum = 0.f;
    for (int n = tid; n < V_; n += 1024) sum += expf(row[n] - mx);
    sh[tid] = sum;
    __syncthreads();
    for (int off = 512; off > 0; off >>= 1) {
        if (tid < off) sh[tid] += sh[tid + off];
        __syncthreads();
    }
    float lse = mx + logf(sh[0]);
    for (int n = tid; n < V_; n += 1024) row[n] -= lse;
}

// ---------------- launch ----------------
extern "C" void kernel_launch(void* const* d_in, const int* in_sizes, int n_in,
                              void* d_out, int out_size) {
    const int*   x    = (const int*)d_in[0];
    const float* lh   = (const float*)d_in[1];   // [1,64,1024]
    const float* enc  = (const float*)d_in[2];   // [512,64,1024]
    const float* embW = (const float*)d_in[3];   // [32000,512]
    const float* attW = (const float*)d_in[4];   // [1024,2048]
    const float* attb = (const float*)d_in[5];   // [1024]
    const float* v    = (const float*)d_in[6];   // [1024]
    const float* Wih  = (const float*)d_in[7];   // [3072,1536]
    const float* Whh  = (const float*)d_in[8];   // [3072,1024]
    const float* bih  = (const float*)d_in[9];
    const float* bhh  = (const float*)d_in[10];
    const float* fcW  = (const float*)d_in[11];  // [32000,2048]
    const float* fcb  = (const float*)d_in[12];

    float* out      = (float*)d_out;
    float* out_logp = out;                         // [64,32000]
    float* out_h    = out + (size_t)B_ * V_;       // [1,64,1024]
    float* out_w    = out_h + (size_t)B_ * H_;     // [64,1,512]

    float *rnn_in, *bias_a, *scores_part, *gi, *gh, *cat2;
    cudaGetSymbolAddress((void**)&rnn_in,      g_rnn_in);
    cudaGetSymbolAddress((void**)&bias_a,      g_bias_a);
    cudaGetSymbolAddress((void**)&scores_part, g_scores_part);
    cudaGetSymbolAddress((void**)&gi,          g_gi);
    cudaGetSymbolAddress((void**)&gh,          g_gh);
    cudaGetSymbolAddress((void**)&cat2,        g_cat2);

    // emb gather (independent of attention path)
    gather_emb_k<<<B_, 128>>>(x, embW, rnn_in);
    // bias_a = attn_b + h @ W1^T   (W1 = attn_W[:, :H])
    gemm_m64_k<<<H_ / 64, 256>>>(lh, H_, attW, 2 * H_, attb, bias_a, H_, H_);
    // big fused energy GEMM -> partial scores
    attn_energy_k<<<dim3(8, 256), 256>>>(enc, attW, bias_a, v, scores_part);
    // softmax over T -> attn_w (output region 3)
    softmax_k<<<B_, 512>>>(scores_part, out_w);
    // context -> rnn_in[:,512:], cat2[:,1024:]
    context_k<<<dim3(H_ / 128, B_), 128>>>(enc, out_w, rnn_in, cat2);
    // GRU input/hidden projections
    gemm_m64_k<<<3 * H_ / 64, 256>>>(rnn_in, E_ + H_, Wih, E_ + H_, bih, gi, 3 * H_, E_ + H_);
    gemm_m64_k<<<3 * H_ / 64, 256>>>(lh, H_, Whh, H_, bhh, gh, 3 * H_, H_);
    // gates -> h_new (output region 2) + cat2[:, :1024]
    gates_k<<<B_, 256>>>(gi, gh, lh, out_h, cat2);
    // fc logits -> output region 1
    gemm_m64_k<<<V_ / 64, 256>>>(cat2, 2 * H_, fcW, 2 * H_, fcb, out_logp, V_, 2 * H_);
    // in-place log_softmax
    logsoftmax_k<<<B_, 1024>>>(out_logp);
}

// round 4
// speedup vs baseline: 1.6200x; 1.6200x over previous
#include <cuda_runtime.h>
#include <cuda_bf16.h>
#include <math.h>
#include <stdint.h>

#define B_ 64
#define T_ 512
#define H_ 1024
#define E_ 512
#define V_ 32000
#define M_BT (B_ * T_)        // 32768

// ---------------- scratch (device globals; no allocation allowed) ----------------
__device__ float g_rnn_in[B_ * (E_ + H_)];      // [64, 1536]  = [emb | context]
__device__ float g_bias_a[B_ * H_];             // attn_b + h @ W1^T   [64, 1024]
__device__ float g_bias_aT[H_ * B_];            // transposed [1024, 64]
__device__ float g_scores[M_BT];                // final scores [t*64+b]
__device__ float g_gi[B_ * 3 * H_];
__device__ float g_gh[B_ * 3 * H_];
__device__ float g_cat2[B_ * 2 * H_];           // [h_new | context]
__device__ __nv_bfloat16 g_enc_hi[M_BT * H_];   // 64 MB
__device__ __nv_bfloat16 g_enc_lo[M_BT * H_];   // 64 MB
__device__ __nv_bfloat16 g_w_hi[H_ * H_];       // 2 MB
__device__ __nv_bfloat16 g_w_lo[H_ * H_];       // 2 MB

// ======================= helpers: cp.async / ldmatrix / mma =======================
__device__ __forceinline__ uint32_t smem_u32(const void* p) {
    uint32_t a;
    asm("{ .reg .u64 t; cvta.to.shared.u64 t, %1; cvt.u32.u64 %0, t; }" : "=r"(a) : "l"(p));
    return a;
}
#define CP_ASYNC16(dst, src) \
    asm volatile("cp.async.cg.shared.global [%0], [%1], 16;" :: "r"(dst), "l"(src))
#define CP_COMMIT() asm volatile("cp.async.commit_group;" ::: "memory")
#define CP_WAIT2() asm volatile("cp.async.wait_group 2;" ::: "memory")
#define CP_WAIT1() asm volatile("cp.async.wait_group 1;" ::: "memory")
#define CP_WAIT0() asm volatile("cp.async.wait_group 0;" ::: "memory")

__device__ __forceinline__ void ldmx4(uint32_t* r, uint32_t addr) {
    asm volatile("ldmatrix.sync.aligned.m8n8.x4.shared.b16 {%0,%1,%2,%3}, [%4];"
                 : "=r"(r[0]), "=r"(r[1]), "=r"(r[2]), "=r"(r[3]) : "r"(addr));
}
__device__ __forceinline__ void mma16816(float* d, const uint32_t* a, uint32_t b0, uint32_t b1) {
    asm volatile("mma.sync.aligned.m16n8k16.row.col.f32.bf16.bf16.f32 "
                 "{%0,%1,%2,%3}, {%4,%5,%6,%7}, {%8,%9}, {%0,%1,%2,%3};"
                 : "+f"(d[0]), "+f"(d[1]), "+f"(d[2]), "+f"(d[3])
                 : "r"(a[0]), "r"(a[1]), "r"(a[2]), "r"(a[3]), "r"(b0), "r"(b1));
}

// ======================= energy kernel tiling =======================
#define KSTEP 32
#define ROWB 80                       // padded row bytes (40 bf16; 32 used)
#define TILE_A (128 * ROWB)           // 10240 bytes per operand tile
#define STAGE_B (4 * TILE_A)          // 40960: A_hi | A_lo | B_hi | B_lo
#define NSTAGE 4
#define SMEM_ENERGY (NSTAGE * STAGE_B + 4 * 128 * 4)   // 163840 + 2048

// ---------------- bf16 hi/lo split conversions ----------------
__global__ void split_enc_k(const float4* __restrict__ in,
                            __nv_bfloat16* __restrict__ hi,
                            __nv_bfloat16* __restrict__ lo) {
    size_t i = (size_t)blockIdx.x * blockDim.x + threadIdx.x;   // < M_BT*H_/4
    float4 x = in[i];
    float xs[4] = {x.x, x.y, x.z, x.w};
    __align__(8) __nv_bfloat16 h[4];
    __align__(8) __nv_bfloat16 l[4];
    #pragma unroll
    for (int j = 0; j < 4; j++) {
        h[j] = __float2bfloat16(xs[j]);
        l[j] = __float2bfloat16(xs[j] - __bfloat162float(h[j]));
    }
    *reinterpret_cast<uint2*>(hi + 4 * i) = *reinterpret_cast<uint2*>(h);
    *reinterpret_cast<uint2*>(lo + 4 * i) = *reinterpret_cast<uint2*>(l);
}

__global__ void split_w_k(const float* __restrict__ attnW,
                          __nv_bfloat16* __restrict__ hi,
                          __nv_bfloat16* __restrict__ lo) {
    int i = blockIdx.x * blockDim.x + threadIdx.x;   // < H_*H_/4
    int r = i >> 8;
    int k4 = i & 255;
    const float4* src = reinterpret_cast<const float4*>(attnW + (size_t)r * (2 * H_) + H_) + k4;
    float4 x = *src;
    float xs[4] = {x.x, x.y, x.z, x.w};
    __align__(8) __nv_bfloat16 h[4];
    __align__(8) __nv_bfloat16 l[4];
    #pragma unroll
    for (int j = 0; j < 4; j++) {
        h[j] = __float2bfloat16(xs[j]);
        l[j] = __float2bfloat16(xs[j] - __bfloat162float(h[j]));
    }
    *reinterpret_cast<uint2*>(hi + 4 * (size_t)i) = *reinterpret_cast<uint2*>(h);
    *reinterpret_cast<uint2*>(lo + 4 * (size_t)i) = *reinterpret_cast<uint2*>(l);
}

// ---------------- K0: embedding gather ----------------
__global__ void gather_emb_k(const int* __restrict__ x,
                             const float* __restrict__ embW,
                             float* __restrict__ rnn_in) {
    int b = blockIdx.x;
    int row = x[b];
    for (int e = threadIdx.x; e < E_; e += blockDim.x)
        rnn_in[b * (E_ + H_) + e] = embW[(size_t)row * E_ + e];
}

// ---------------- generic M=64 GEMM (fp32 CUDA cores) ----------------
__global__ void gemm_m64_k(const float* __restrict__ A, int lda,
                           const float* __restrict__ W, int ldw,
                           const float* __restrict__ bias,
                           float* __restrict__ C, int ldc, int K) {
    __shared__ float As[16][64];
    __shared__ float Ws[16][64];
    const int tid = threadIdx.x;
    const int n0 = blockIdx.x * 64;
    const int lrow = tid >> 2;
    const int kq = (tid & 3) * 4;
    const int ty = tid >> 4;
    const int tx = tid & 15;

    float acc[4][4] = {};
    for (int kk = 0; kk < K; kk += 16) {
        float4 av = *(const float4*)&A[lrow * lda + kk + kq];
        float4 wv = *(const float4*)&W[(size_t)(n0 + lrow) * ldw + kk + kq];
        __syncthreads();
        As[kq + 0][lrow] = av.x; As[kq + 1][lrow] = av.y;
        As[kq + 2][lrow] = av.z; As[kq + 3][lrow] = av.w;
        Ws[kq + 0][lrow] = wv.x; Ws[kq + 1][lrow] = wv.y;
        Ws[kq + 2][lrow] = wv.z; Ws[kq + 3][lrow] = wv.w;
        __syncthreads();
        #pragma unroll
        for (int k = 0; k < 16; k++) {
            float4 a = *(const float4*)&As[k][ty * 4];
            float4 w = *(const float4*)&Ws[k][tx * 4];
            float af[4] = {a.x, a.y, a.z, a.w};
            float wf[4] = {w.x, w.y, w.z, w.w};
            #pragma unroll
            for (int i = 0; i < 4; i++)
                #pragma unroll
                for (int j = 0; j < 4; j++)
                    acc[i][j] = fmaf(af[i], wf[j], acc[i][j]);
        }
    }
    #pragma unroll
    for (int i = 0; i < 4; i++) {
        int m = ty * 4 + i;
        #pragma unroll
        for (int j = 0; j < 4; j++) {
            int n = n0 + tx * 4 + j;
            C[(size_t)m * ldc + n] = acc[i][j] + bias[n];
        }
    }
}

// ---------------- transpose bias_a [64,1024] -> [1024,64] ----------------
__global__ void transpose_bias_k(const float* __restrict__ in, float* __restrict__ out) {
    __shared__ float t[32][33];
    int h0 = blockIdx.x * 32, b0 = blockIdx.y * 32;
    t[threadIdx.y][threadIdx.x] = in[(b0 + threadIdx.y) * H_ + h0 + threadIdx.x];
    __syncthreads();
    out[(h0 + threadIdx.y) * B_ + b0 + threadIdx.x] = t[threadIdx.x][threadIdx.y];
}

// ---------------- K2: mma.sync energy GEMM + fused relu*v reduction ----------------
// CTA: 128 rows (m) x 128 cols (h) per chunk, 8 chunks (full N=1024), K=1024.
// bf16 hi/lo 3-pass: A_hi*B_hi + A_hi*B_lo + A_lo*B_hi  (fp32 acc).
// scores[m] = sum_h relu(D[m,h] + biasT[h][m&63]) * v[h], reduced in registers.
__global__ void __launch_bounds__(256, 1)
energy_mma_k(const __nv_bfloat16* __restrict__ ehi, const __nv_bfloat16* __restrict__ elo,
             const __nv_bfloat16* __restrict__ whi, const __nv_bfloat16* __restrict__ wlo,
             const float* __restrict__ biasT, const float* __restrict__ v,
             float* __restrict__ scores) {
    extern __shared__ char sm[];
    const uint32_t sb = smem_u32(sm);
    float* red = (float*)(sm + NSTAGE * STAGE_B);

    const int tid = threadIdx.x;
    const int wid = tid >> 5;
    const int lane = tid & 31;
    const int m0 = blockIdx.x * 128;
    const int mw = wid >> 2;      // 0..1  (rows mw*64 .. +63)
    const int nw = wid & 3;       // 0..3  (cols nw*32 .. +31 within chunk)

    // ldmatrix lane addressing precompute
    const int a_l = lane & 15;
    const int a_kh = (lane >> 4) << 3;            // 0 or 8
    const int b_nb = (lane & 7) + ((lane >> 4) << 3);
    const int b_kh = ((lane >> 3) & 1) << 3;

    const int g = lane >> 2;                      // 0..7 (row in 8-group)
    const int t2 = (lane & 3) << 1;               // col pair base

    float acc[4][4][4];
    float rowsum[8];
    #pragma unroll
    for (int i = 0; i < 8; i++) rowsum[i] = 0.f;

    const int total_it = 8 * 32;

    // per-thread cp.async assignment: 4 operands x 2 halves, idx = tid + h*256
    const int ld_r = tid >> 2;
    const int ld_c = tid & 3;
    const int ld_r2 = (tid + 256) >> 2;
    const int ld_c2 = (tid + 256) & 3;

    #define ISSUE_LOAD(it_) do {                                                   \
        int chunk_ = (it_) >> 5;                                                   \
        int kbase_ = ((it_) & 31) * KSTEP;                                         \
        uint32_t stg_ = sb + ((it_) & (NSTAGE - 1)) * STAGE_B;                     \
        const __nv_bfloat16* s0 = ehi + (size_t)m0 * H_ + kbase_;                  \
        const __nv_bfloat16* s1 = elo + (size_t)m0 * H_ + kbase_;                  \
        const __nv_bfloat16* s2 = whi + (size_t)(chunk_ * 128) * H_ + kbase_;      \
        const __nv_bfloat16* s3 = wlo + (size_t)(chunk_ * 128) * H_ + kbase_;      \
        const __nv_bfloat16* ss[4] = {s0, s1, s2, s3};                             \
        _Pragma("unroll")                                                          \
        for (int op = 0; op < 4; op++) {                                           \
            CP_ASYNC16(stg_ + op * TILE_A + ld_r * ROWB + ld_c * 16,               \
                       ss[op] + (size_t)ld_r * H_ + ld_c * 8);                     \
            CP_ASYNC16(stg_ + op * TILE_A + ld_r2 * ROWB + ld_c2 * 16,             \
                       ss[op] + (size_t)ld_r2 * H_ + ld_c2 * 8);                   \
        }                                                                          \
        CP_COMMIT();                                                               \
    } while (0)

    ISSUE_LOAD(0);
    ISSUE_LOAD(1);

    for (int it = 0; it < total_it; it++) {
        const int kt = it & 31;
        const int chunk = it >> 5;
        if (kt == 0) {
            #pragma unroll
            for (int mt = 0; mt < 4; mt++)
                #pragma unroll
                for (int nt = 0; nt < 4; nt++)
                    #pragma unroll
                    for (int k = 0; k < 4; k++) acc[mt][nt][k] = 0.f;
        }
        if (it + 2 < total_it) { ISSUE_LOAD(it + 2); CP_WAIT2(); }
        else if (it + 1 < total_it) { CP_WAIT1(); }
        else { CP_WAIT0(); }
        __syncthreads();

        const uint32_t stg = sb + (it & (NSTAGE - 1)) * STAGE_B;
        const uint32_t aHiB = stg;
        const uint32_t aLoB = stg + TILE_A;
        const uint32_t bHiB = stg + 2 * TILE_A;
        const uint32_t bLoB = stg + 3 * TILE_A;

        #pragma unroll
        for (int ks = 0; ks < 2; ks++) {
            uint32_t Ahi[4][4], Alo[4][4];
            #pragma unroll
            for (int mt = 0; mt < 4; mt++) {
                uint32_t off = (uint32_t)((mw * 64 + mt * 16 + a_l) * ROWB + (ks * 16 + a_kh) * 2);
                ldmx4(Ahi[mt], aHiB + off);
                ldmx4(Alo[mt], aLoB + off);
            }
            uint32_t Bhi[2][4], Blo[2][4];
            #pragma unroll
            for (int np = 0; np < 2; np++) {
                uint32_t off = (uint32_t)((nw * 32 + np * 16 + b_nb) * ROWB + (ks * 16 + b_kh) * 2);
                ldmx4(Bhi[np], bHiB + off);
                ldmx4(Blo[np], bLoB + off);
            }
            #pragma unroll
            for (int mt = 0; mt < 4; mt++)
                #pragma unroll
                for (int nt = 0; nt < 4; nt++) {
                    const int np = nt >> 1, pr = (nt & 1) * 2;
                    mma16816(acc[mt][nt], Ahi[mt], Bhi[np][pr], Bhi[np][pr + 1]);
                    mma16816(acc[mt][nt], Ahi[mt], Blo[np][pr], Blo[np][pr + 1]);
                    mma16816(acc[mt][nt], Alo[mt], Bhi[np][pr], Bhi[np][pr + 1]);
                }
        }

        if (kt == 31) {
            // epilogue for this chunk: bias + relu + *v, accumulate row sums in regs
            #pragma unroll
            for (int nt = 0; nt < 4; nt++) {
                const int col0 = chunk * 128 + nw * 32 + nt * 8 + t2;
                const float v0 = __ldg(&v[col0]);
                const float v1 = __ldg(&v[col0 + 1]);
                #pragma unroll
                for (int mt = 0; mt < 4; mt++) {
                    #pragma unroll
                    for (int i = 0; i < 2; i++) {
                        const int row = mw * 64 + mt * 16 + g + i * 8;
                        const int b = row & (B_ - 1);
                        float e0 = acc[mt][nt][i * 2 + 0] + __ldg(&biasT[(size_t)col0 * B_ + b]);
                        float e1 = acc[mt][nt][i * 2 + 1] + __ldg(&biasT[(size_t)(col0 + 1) * B_ + b]);
                        rowsum[mt * 2 + i] += fmaxf(e0, 0.f) * v0 + fmaxf(e1, 0.f) * v1;
                    }
                }
            }
        }
    }

    // cross-lane reduce (lanes in same quad share rows, differ in cols)
    #pragma unroll
    for (int k = 0; k < 8; k++) {
        rowsum[k] += __shfl_xor_sync(0xFFFFFFFF, rowsum[k], 1);
        rowsum[k] += __shfl_xor_sync(0xFFFFFFFF, rowsum[k], 2);
    }
    __syncthreads();
    if ((lane & 3) == 0) {
        #pragma unroll
        for (int mt = 0; mt < 4; mt++)
            #pragma unroll
            for (int i = 0; i < 2; i++)
                red[nw * 128 + mw * 64 + mt * 16 + g + i * 8] = rowsum[mt * 2 + i];
    }
    __syncthreads();
    if (tid < 128) {
        float s = red[tid] + red[128 + tid] + red[256 + tid] + red[384 + tid];
        scores[m0 + tid] = s;
    }
    #undef ISSUE_LOAD
}

// ---------------- K3: softmax over T, writes attn_w output ----------------
__global__ void softmax_k(const float* __restrict__ scores,
                          float* __restrict__ attn_w_out) {
    int b = blockIdx.x;
    int t = threadIdx.x;
    __shared__ float sh[512];
    float s = scores[t * B_ + b];
    sh[t] = s;
    __syncthreads();
    for (int off = 256; off > 0; off >>= 1) {
        if (t < off) sh[t] = fmaxf(sh[t], sh[t + off]);
        __syncthreads();
    }
    float mx = sh[0];
    __syncthreads();
    float e = expf(s - mx);
    sh[t] = e;
    __syncthreads();
    for (int off = 256; off > 0; off >>= 1) {
        if (t < off) sh[t] += sh[t + off];
        __syncthreads();
    }
    attn_w_out[b * T_ + t] = e / sh[0];
}

// ---------------- K4: context = attn_w @ enc ----------------
__global__ void context_k(const float* __restrict__ enc,
                          const float* __restrict__ attn_w,
                          float* __restrict__ rnn_in,
                          float* __restrict__ cat2) {
    int b = blockIdx.y;
    int h = blockIdx.x * 128 + threadIdx.x;
    __shared__ float w[T_];
    for (int t = threadIdx.x; t < T_; t += 128) w[t] = attn_w[b * T_ + t];
    __syncthreads();
    float acc = 0.f;
    #pragma unroll 4
    for (int t = 0; t < T_; t++)
        acc = fmaf(w[t], enc[(size_t)(t * B_ + b) * H_ + h], acc);
    rnn_in[b * (E_ + H_) + E_ + h] = acc;
    cat2[b * (2 * H_) + H_ + h] = acc;
}

// ---------------- K6: GRU gates ----------------
__global__ void gates_k(const float* __restrict__ gi,
                        const float* __restrict__ gh,
                        const float* __restrict__ lh,
                        float* __restrict__ hnew_out,
                        float* __restrict__ cat2) {
    int b = blockIdx.x;
    for (int h = threadIdx.x; h < H_; h += blockDim.x) {
        float r = 1.f / (1.f + expf(-(gi[b * 3 * H_ + h] + gh[b * 3 * H_ + h])));
        float z = 1.f / (1.f + expf(-(gi[b * 3 * H_ + H_ + h] + gh[b * 3 * H_ + H_ + h])));
        float n = tanhf(gi[b * 3 * H_ + 2 * H_ + h] + r * gh[b * 3 * H_ + 2 * H_ + h]);
        float hp = lh[b * H_ + h];
        float hn = (1.f - z) * n + z * hp;
        hnew_out[b * H_ + h] = hn;
        cat2[b * (2 * H_) + h] = hn;
    }
}

// ---------------- K8: in-place log_softmax on logits rows ----------------
__global__ void logsoftmax_k(float* __restrict__ logits) {
    int b = blockIdx.x;
    int tid = threadIdx.x;
    __shared__ float sh[1024];
    float* row = logits + (size_t)b * V_;
    float mx = -1e30f;
    for (int n = tid; n < V_; n += 1024) mx = fmaxf(mx, row[n]);
    sh[tid] = mx;
    __syncthreads();
    for (int off = 512; off > 0; off >>= 1) {
        if (tid < off) sh[tid] = fmaxf(sh[tid], sh[tid + off]);
        __syncthreads();
    }
    mx = sh[0];
    __syncthreads();
    float sum = 0.f;
    for (int n = tid; n < V_; n += 1024) sum += expf(row[n] - mx);
    sh[tid] = sum;
    __syncthreads();
    for (int off = 512; off > 0; off >>= 1) {
        if (tid < off) sh[tid] += sh[tid + off];
        __syncthreads();
    }
    float lse = mx + logf(sh[0]);
    for (int n = tid; n < V_; n += 1024) row[n] -= lse;
}

// ---------------- launch ----------------
extern "C" void kernel_launch(void* const* d_in, const int* in_sizes, int n_in,
                              void* d_out, int out_size) {
    const int*   x    = (const int*)d_in[0];
    const float* lh   = (const float*)d_in[1];   // [1,64,1024]
    const float* enc  = (const float*)d_in[2];   // [512,64,1024]
    const float* embW = (const float*)d_in[3];   // [32000,512]
    const float* attW = (const float*)d_in[4];   // [1024,2048]
    const float* attb = (const float*)d_in[5];   // [1024]
    const float* v    = (const float*)d_in[6];   // [1024]
    const float* Wih  = (const float*)d_in[7];   // [3072,1536]
    const float* Whh  = (const float*)d_in[8];   // [3072,1024]
    const float* bih  = (const float*)d_in[9];
    const float* bhh  = (const float*)d_in[10];
    const float* fcW  = (const float*)d_in[11];  // [32000,2048]
    const float* fcb  = (const float*)d_in[12];

    float* out      = (float*)d_out;
    float* out_logp = out;                         // [64,32000]
    float* out_h    = out + (size_t)B_ * V_;       // [1,64,1024]
    float* out_w    = out_h + (size_t)B_ * H_;     // [64,1,512]

    float *rnn_in, *bias_a, *bias_aT, *scoresp, *gi, *gh, *cat2;
    __nv_bfloat16 *ehi, *elo, *whi, *wlo;
    cudaGetSymbolAddress((void**)&rnn_in,  g_rnn_in);
    cudaGetSymbolAddress((void**)&bias_a,  g_bias_a);
    cudaGetSymbolAddress((void**)&bias_aT, g_bias_aT);
    cudaGetSymbolAddress((void**)&scoresp, g_scores);
    cudaGetSymbolAddress((void**)&gi,      g_gi);
    cudaGetSymbolAddress((void**)&gh,      g_gh);
    cudaGetSymbolAddress((void**)&cat2,    g_cat2);
    cudaGetSymbolAddress((void**)&ehi,     g_enc_hi);
    cudaGetSymbolAddress((void**)&elo,     g_enc_lo);
    cudaGetSymbolAddress((void**)&whi,     g_w_hi);
    cudaGetSymbolAddress((void**)&wlo,     g_w_lo);

    cudaFuncSetAttribute(energy_mma_k, cudaFuncAttributeMaxDynamicSharedMemorySize, SMEM_ENERGY);

    // bf16 hi/lo splits
    split_enc_k<<<(M_BT * H_ / 4) / 256, 256>>>((const float4*)enc, ehi, elo);
    split_w_k<<<(H_ * H_ / 4) / 256, 256>>>(attW, whi, wlo);
    // emb gather
    gather_emb_k<<<B_, 128>>>(x, embW, rnn_in);
    // bias_a = attn_b + h @ W1^T, then transpose
    gemm_m64_k<<<H_ / 64, 256>>>(lh, H_, attW, 2 * H_, attb, bias_a, H_, H_);
    transpose_bias_k<<<dim3(H_ / 32, B_ / 32), dim3(32, 32)>>>(bias_a, bias_aT);
    // mma.sync energy GEMM + fused score reduction
    energy_mma_k<<<M_BT / 128, 256, SMEM_ENERGY>>>(ehi, elo, whi, wlo, bias_aT, v, scoresp);
    // softmax over T -> attn_w
    softmax_k<<<B_, 512>>>(scoresp, out_w);
    // context
    context_k<<<dim3(H_ / 128, B_), 128>>>(enc, out_w, rnn_in, cat2);
    // GRU projections
    gemm_m64_k<<<3 * H_ / 64, 256>>>(rnn_in, E_ + H_, Wih, E_ + H_, bih, gi, 3 * H_, E_ + H_);
    gemm_m64_k<<<3 * H_ / 64, 256>>>(lh, H_, Whh, H_, bhh, gh, 3 * H_, H_);
    // gates
    gates_k<<<B_, 256>>>(gi, gh, lh, out_h, cat2);
    // fc logits (fp32)
    gemm_m64_k<<<V_ / 64, 256>>>(cat2, 2 * H_, fcW, 2 * H_, fcb, out_logp, V_, 2 * H_);
    // log_softmax
    logsoftmax_k<<<B_, 1024>>>(out_logp);
}

// round 5
// speedup vs baseline: 2.0685x; 1.2769x over previous
#include <cuda_runtime.h>
#include <cuda_bf16.h>
#include <math.h>
#include <stdint.h>

#define B_ 64
#define T_ 512
#define H_ 1024
#define E_ 512
#define V_ 32000
#define M_BT (B_ * T_)        // 32768

// ---------------- scratch (device globals; no allocation allowed) ----------------
__device__ float g_rnn_in[B_ * (E_ + H_)];        // [64, 1536]  = [emb | context]
__device__ float g_bias_aT[H_ * B_];              // transposed [1024, 64]
__device__ float g_scores[M_BT];                  // final scores [t*64+b]
__device__ float g_cat2[B_ * 2 * H_];             // [h_new | context]
__device__ float g_part_bias[8 * B_ * H_];        // k-split partials
__device__ float g_part_gi[4 * B_ * 3 * H_];
__device__ float g_part_gh[4 * B_ * 3 * H_];
__device__ __nv_bfloat16 g_enc_hi[M_BT * H_];     // 64 MB
__device__ __nv_bfloat16 g_enc_lo[M_BT * H_];     // 64 MB
__device__ __nv_bfloat16 g_w_hi[H_ * H_];         // 2 MB
__device__ __nv_bfloat16 g_w_lo[H_ * H_];         // 2 MB
__device__ __nv_bfloat16 g_fc_hi[(size_t)V_ * 2 * H_];   // 131 MB
__device__ __nv_bfloat16 g_fc_lo[(size_t)V_ * 2 * H_];   // 131 MB
__device__ __nv_bfloat16 g_cat2_hi[B_ * 2 * H_];
__device__ __nv_bfloat16 g_cat2_lo[B_ * 2 * H_];

// ======================= helpers: cp.async / ldmatrix / mma =======================
__device__ __forceinline__ uint32_t smem_u32(const void* p) {
    uint32_t a;
    asm("{ .reg .u64 t; cvta.to.shared.u64 t, %1; cvt.u32.u64 %0, t; }" : "=r"(a) : "l"(p));
    return a;
}
#define CP_ASYNC16(dst, src) \
    asm volatile("cp.async.cg.shared.global [%0], [%1], 16;" :: "r"(dst), "l"(src))
#define CP_COMMIT() asm volatile("cp.async.commit_group;" ::: "memory")
#define CP_WAIT2() asm volatile("cp.async.wait_group 2;" ::: "memory")
#define CP_WAIT1() asm volatile("cp.async.wait_group 1;" ::: "memory")
#define CP_WAIT0() asm volatile("cp.async.wait_group 0;" ::: "memory")

__device__ __forceinline__ void ldmx4(uint32_t* r, uint32_t addr) {
    asm volatile("ldmatrix.sync.aligned.m8n8.x4.shared.b16 {%0,%1,%2,%3}, [%4];"
                 : "=r"(r[0]), "=r"(r[1]), "=r"(r[2]), "=r"(r[3]) : "r"(addr));
}
__device__ __forceinline__ void mma16816(float* d, const uint32_t* a, uint32_t b0, uint32_t b1) {
    asm volatile("mma.sync.aligned.m16n8k16.row.col.f32.bf16.bf16.f32 "
                 "{%0,%1,%2,%3}, {%4,%5,%6,%7}, {%8,%9}, {%0,%1,%2,%3};"
                 : "+f"(d[0]), "+f"(d[1]), "+f"(d[2]), "+f"(d[3])
                 : "r"(a[0]), "r"(a[1]), "r"(a[2]), "r"(a[3]), "r"(b0), "r"(b1));
}

// ======================= energy kernel tiling =======================
#define KSTEP 32
#define ROWB 80
#define TILE_A (128 * ROWB)           // 10240
#define STAGE_B (4 * TILE_A)          // 40960
#define NSTAGE 4
#define SMEM_ENERGY (NSTAGE * STAGE_B + 4 * 128 * 4)

// ======================= fc kernel tiling =======================
#define TILE_AF (64 * ROWB)           // 5120
#define TILE_BF (128 * ROWB)          // 10240
#define FC_AHI 0
#define FC_ALO TILE_AF
#define FC_BHI (2 * TILE_AF)
#define FC_BLO (2 * TILE_AF + TILE_BF)
#define STAGE_F (2 * TILE_AF + 2 * TILE_BF)   // 30720
#define SMEM_FC (4 * STAGE_F)                 // 122880

// ---------------- generic flat fp32 -> bf16 hi/lo split ----------------
__global__ void split_flat_k(const float4* __restrict__ in,
                             __nv_bfloat16* __restrict__ hi,
                             __nv_bfloat16* __restrict__ lo) {
    size_t i = (size_t)blockIdx.x * blockDim.x + threadIdx.x;
    float4 x = in[i];
    float xs[4] = {x.x, x.y, x.z, x.w};
    __align__(8) __nv_bfloat16 h[4];
    __align__(8) __nv_bfloat16 l[4];
    #pragma unroll
    for (int j = 0; j < 4; j++) {
        h[j] = __float2bfloat16(xs[j]);
        l[j] = __float2bfloat16(xs[j] - __bfloat162float(h[j]));
    }
    *reinterpret_cast<uint2*>(hi + 4 * i) = *reinterpret_cast<uint2*>(h);
    *reinterpret_cast<uint2*>(lo + 4 * i) = *reinterpret_cast<uint2*>(l);
}

__global__ void split_w_k(const float* __restrict__ attnW,
                          __nv_bfloat16* __restrict__ hi,
                          __nv_bfloat16* __restrict__ lo) {
    int i = blockIdx.x * blockDim.x + threadIdx.x;   // < H_*H_/4
    int r = i >> 8;
    int k4 = i & 255;
    const float4* src = reinterpret_cast<const float4*>(attnW + (size_t)r * (2 * H_) + H_) + k4;
    float4 x = *src;
    float xs[4] = {x.x, x.y, x.z, x.w};
    __align__(8) __nv_bfloat16 h[4];
    __align__(8) __nv_bfloat16 l[4];
    #pragma unroll
    for (int j = 0; j < 4; j++) {
        h[j] = __float2bfloat16(xs[j]);
        l[j] = __float2bfloat16(xs[j] - __bfloat162float(h[j]));
    }
    *reinterpret_cast<uint2*>(hi + 4 * (size_t)i) = *reinterpret_cast<uint2*>(h);
    *reinterpret_cast<uint2*>(lo + 4 * (size_t)i) = *reinterpret_cast<uint2*>(l);
}

// ---------------- K0: embedding gather ----------------
__global__ void gather_emb_k(const int* __restrict__ x,
                             const float* __restrict__ embW,
                             float* __restrict__ rnn_in) {
    int b = blockIdx.x;
    int row = x[b];
    for (int e = threadIdx.x; e < E_; e += blockDim.x)
        rnn_in[b * (E_ + H_) + e] = embW[(size_t)row * E_ + e];
}

// ---------------- K-split M=64 GEMM: Cp[ks][64][N] = A[64, ksl] @ W[N, ksl]^T ----------------
__global__ void gemm_m64_ks(const float* __restrict__ A, int lda,
                            const float* __restrict__ W, int ldw,
                            float* __restrict__ Cp, int ldc, int kc) {
    __shared__ float As[16][64];
    __shared__ float Ws[16][64];
    const int tid = threadIdx.x;
    const int n0 = blockIdx.x * 64;
    const int kk0 = blockIdx.y * kc;
    const int lrow = tid >> 2;
    const int kq = (tid & 3) * 4;
    const int ty = tid >> 4;
    const int tx = tid & 15;

    float acc[4][4] = {};
    for (int kk = kk0; kk < kk0 + kc; kk += 16) {
        float4 av = *(const float4*)&A[lrow * lda + kk + kq];
        float4 wv = *(const float4*)&W[(size_t)(n0 + lrow) * ldw + kk + kq];
        __syncthreads();
        As[kq + 0][lrow] = av.x; As[kq + 1][lrow] = av.y;
        As[kq + 2][lrow] = av.z; As[kq + 3][lrow] = av.w;
        Ws[kq + 0][lrow] = wv.x; Ws[kq + 1][lrow] = wv.y;
        Ws[kq + 2][lrow] = wv.z; Ws[kq + 3][lrow] = wv.w;
        __syncthreads();
        #pragma unroll
        for (int k = 0; k < 16; k++) {
            float4 a = *(const float4*)&As[k][ty * 4];
            float4 w = *(const float4*)&Ws[k][tx * 4];
            float af[4] = {a.x, a.y, a.z, a.w};
            float wf[4] = {w.x, w.y, w.z, w.w};
            #pragma unroll
            for (int i = 0; i < 4; i++)
                #pragma unroll
                for (int j = 0; j < 4; j++)
                    acc[i][j] = fmaf(af[i], wf[j], acc[i][j]);
        }
    }
    #pragma unroll
    for (int i = 0; i < 4; i++) {
        int m = blockIdx.y * 64 + ty * 4 + i;
        #pragma unroll
        for (int j = 0; j < 4; j++)
            Cp[(size_t)m * ldc + n0 + tx * 4 + j] = acc[i][j];
    }
}

// ---------------- bias partial reduce + transpose: biasT[h][b] ----------------
__global__ void bias_redT_k(const float* __restrict__ part,
                            const float* __restrict__ attb,
                            float* __restrict__ biasT) {
    int idx = blockIdx.x * 256 + threadIdx.x;   // 65536
    int b = idx >> 10, h = idx & 1023;
    float s = attb[h];
    #pragma unroll
    for (int ks = 0; ks < 8; ks++)
        s += part[(size_t)((ks << 6) + b) * H_ + h];
    biasT[h * B_ + b] = s;
}

// ---------------- K2: mma.sync energy GEMM + fused relu*v reduction ----------------
__global__ void __launch_bounds__(256, 1)
energy_mma_k(const __nv_bfloat16* __restrict__ ehi, const __nv_bfloat16* __restrict__ elo,
             const __nv_bfloat16* __restrict__ whi, const __nv_bfloat16* __restrict__ wlo,
             const float* __restrict__ biasT, const float* __restrict__ v,
             float* __restrict__ scores) {
    extern __shared__ char sm[];
    const uint32_t sb = smem_u32(sm);
    float* red = (float*)(sm + NSTAGE * STAGE_B);

    const int tid = threadIdx.x;
    const int wid = tid >> 5;
    const int lane = tid & 31;
    const int m0 = blockIdx.x * 128;
    const int mw = wid >> 2;
    const int nw = wid & 3;

    const int a_l = lane & 15;
    const int a_kh = (lane >> 4) << 3;
    const int b_nb = (lane & 7) + ((lane >> 4) << 3);
    const int b_kh = ((lane >> 3) & 1) << 3;
    const int g = lane >> 2;
    const int t2 = (lane & 3) << 1;

    float acc[4][4][4];
    float rowsum[8];
    #pragma unroll
    for (int i = 0; i < 8; i++) rowsum[i] = 0.f;

    const int total_it = 8 * 32;
    const int ld_r = tid >> 2;
    const int ld_c = tid & 3;
    const int ld_r2 = (tid + 256) >> 2;
    const int ld_c2 = (tid + 256) & 3;

    #define EN_ISSUE(it_) do {                                                     \
        int chunk_ = (it_) >> 5;                                                   \
        int kbase_ = ((it_) & 31) * KSTEP;                                         \
        uint32_t stg_ = sb + ((it_) & (NSTAGE - 1)) * STAGE_B;                     \
        const __nv_bfloat16* s0 = ehi + (size_t)m0 * H_ + kbase_;                  \
        const __nv_bfloat16* s1 = elo + (size_t)m0 * H_ + kbase_;                  \
        const __nv_bfloat16* s2 = whi + (size_t)(chunk_ * 128) * H_ + kbase_;      \
        const __nv_bfloat16* s3 = wlo + (size_t)(chunk_ * 128) * H_ + kbase_;      \
        const __nv_bfloat16* ss[4] = {s0, s1, s2, s3};                             \
        _Pragma("unroll")                                                          \
        for (int op = 0; op < 4; op++) {                                           \
            CP_ASYNC16(stg_ + op * TILE_A + ld_r * ROWB + ld_c * 16,               \
                       ss[op] + (size_t)ld_r * H_ + ld_c * 8);                     \
            CP_ASYNC16(stg_ + op * TILE_A + ld_r2 * ROWB + ld_c2 * 16,             \
                       ss[op] + (size_t)ld_r2 * H_ + ld_c2 * 8);                   \
        }                                                                          \
        CP_COMMIT();                                                               \
    } while (0)

    EN_ISSUE(0);
    EN_ISSUE(1);

    for (int it = 0; it < total_it; it++) {
        const int kt = it & 31;
        const int chunk = it >> 5;
        if (kt == 0) {
            #pragma unroll
            for (int mt = 0; mt < 4; mt++)
                #pragma unroll
                for (int nt = 0; nt < 4; nt++)
                    #pragma unroll
                    for (int k = 0; k < 4; k++) acc[mt][nt][k] = 0.f;
        }
        if (it + 2 < total_it) { EN_ISSUE(it + 2); CP_WAIT2(); }
        else if (it + 1 < total_it) { CP_WAIT1(); }
        else { CP_WAIT0(); }
        __syncthreads();

        const uint32_t stg = sb + (it & (NSTAGE - 1)) * STAGE_B;
        const uint32_t aHiB = stg;
        const uint32_t aLoB = stg + TILE_A;
        const uint32_t bHiB = stg + 2 * TILE_A;
        const uint32_t bLoB = stg + 3 * TILE_A;

        #pragma unroll
        for (int ks = 0; ks < 2; ks++) {
            uint32_t Ahi[4][4], Alo[4][4];
            #pragma unroll
            for (int mt = 0; mt < 4; mt++) {
                uint32_t off = (uint32_t)((mw * 64 + mt * 16 + a_l) * ROWB + (ks * 16 + a_kh) * 2);
                ldmx4(Ahi[mt], aHiB + off);
                ldmx4(Alo[mt], aLoB + off);
            }
            uint32_t Bhi[2][4], Blo[2][4];
            #pragma unroll
            for (int np = 0; np < 2; np++) {
                uint32_t off = (uint32_t)((nw * 32 + np * 16 + b_nb) * ROWB + (ks * 16 + b_kh) * 2);
                ldmx4(Bhi[np], bHiB + off);
                ldmx4(Blo[np], bLoB + off);
            }
            #pragma unroll
            for (int mt = 0; mt < 4; mt++)
                #pragma unroll
                for (int nt = 0; nt < 4; nt++) {
                    const int np = nt >> 1, pr = (nt & 1) * 2;
                    mma16816(acc[mt][nt], Ahi[mt], Bhi[np][pr], Bhi[np][pr + 1]);
                    mma16816(acc[mt][nt], Ahi[mt], Blo[np][pr], Blo[np][pr + 1]);
                    mma16816(acc[mt][nt], Alo[mt], Bhi[np][pr], Bhi[np][pr + 1]);
                }
        }

        if (kt == 31) {
            #pragma unroll
            for (int nt = 0; nt < 4; nt++) {
                const int col0 = chunk * 128 + nw * 32 + nt * 8 + t2;
                const float v0 = __ldg(&v[col0]);
                const float v1 = __ldg(&v[col0 + 1]);
                #pragma unroll
                for (int mt = 0; mt < 4; mt++) {
                    #pragma unroll
                    for (int i = 0; i < 2; i++) {
                        const int row = mw * 64 + mt * 16 + g + i * 8;
                        const int b = row & (B_ - 1);
                        float e0 = acc[mt][nt][i * 2 + 0] + __ldg(&biasT[(size_t)col0 * B_ + b]);
                        float e1 = acc[mt][nt][i * 2 + 1] + __ldg(&biasT[(size_t)(col0 + 1) * B_ + b]);
                        rowsum[mt * 2 + i] += fmaxf(e0, 0.f) * v0 + fmaxf(e1, 0.f) * v1;
                    }
                }
            }
        }
    }

    #pragma unroll
    for (int k = 0; k < 8; k++) {
        rowsum[k] += __shfl_xor_sync(0xFFFFFFFF, rowsum[k], 1);
        rowsum[k] += __shfl_xor_sync(0xFFFFFFFF, rowsum[k], 2);
    }
    __syncthreads();
    if ((lane & 3) == 0) {
        #pragma unroll
        for (int mt = 0; mt < 4; mt++)
            #pragma unroll
            for (int i = 0; i < 2; i++)
                red[nw * 128 + mw * 64 + mt * 16 + g + i * 8] = rowsum[mt * 2 + i];
    }
    __syncthreads();
    if (tid < 128) {
        float s = red[tid] + red[128 + tid] + red[256 + tid] + red[384 + tid];
        scores[m0 + tid] = s;
    }
    #undef EN_ISSUE
}

// ---------------- fc GEMM: logits[64, 32000] = cat2[64,2048] @ fcW^T + fcb ----------------
// bf16 hi/lo 3-pass mma, BM=64, BN=128, BK=32, 4-stage cp.async.
__global__ void __launch_bounds__(256, 1)
fc_mma_k(const __nv_bfloat16* __restrict__ ahi, const __nv_bfloat16* __restrict__ alo,
         const __nv_bfloat16* __restrict__ whi, const __nv_bfloat16* __restrict__ wlo,
         const float* __restrict__ fcb, float* __restrict__ logits) {
    extern __shared__ char sm[];
    const uint32_t sb = smem_u32(sm);

    const int tid = threadIdx.x;
    const int wid = tid >> 5;
    const int lane = tid & 31;
    const int n0 = blockIdx.x * 128;
    const int mw = wid >> 2;       // 0..1: rows mw*32
    const int nw = wid & 3;        // 0..3: cols nw*32

    const int a_l = lane & 15;
    const int a_kh = (lane >> 4) << 3;
    const int b_nb = (lane & 7) + ((lane >> 4) << 3);
    const int b_kh = ((lane >> 3) & 1) << 3;
    const int g = lane >> 2;
    const int t2 = (lane & 3) << 1;

    float acc[2][4][4];
    #pragma unroll
    for (int mt = 0; mt < 2; mt++)
        #pragma unroll
        for (int nt = 0; nt < 4; nt++)
            #pragma unroll
            for (int k = 0; k < 4; k++) acc[mt][nt][k] = 0.f;

    const int ld_r = tid >> 2;     // 0..63
    const int ld_c = tid & 3;

    #define FC_ISSUE(it_) do {                                                      \
        int kb_ = (it_) * 32;                                                       \
        uint32_t stg_ = sb + ((it_) & 3) * STAGE_F;                                 \
        CP_ASYNC16(stg_ + FC_AHI + ld_r * ROWB + ld_c * 16,                         \
                   ahi + (size_t)ld_r * (2 * H_) + kb_ + ld_c * 8);                 \
        CP_ASYNC16(stg_ + FC_ALO + ld_r * ROWB + ld_c * 16,                         \
                   alo + (size_t)ld_r * (2 * H_) + kb_ + ld_c * 8);                 \
        CP_ASYNC16(stg_ + FC_BHI + ld_r * ROWB + ld_c * 16,                         \
                   whi + (size_t)(n0 + ld_r) * (2 * H_) + kb_ + ld_c * 8);          \
        CP_ASYNC16(stg_ + FC_BHI + (ld_r + 64) * ROWB + ld_c * 16,                  \
                   whi + (size_t)(n0 + ld_r + 64) * (2 * H_) + kb_ + ld_c * 8);     \
        CP_ASYNC16(stg_ + FC_BLO + ld_r * ROWB + ld_c * 16,                         \
                   wlo + (size_t)(n0 + ld_r) * (2 * H_) + kb_ + ld_c * 8);          \
        CP_ASYNC16(stg_ + FC_BLO + (ld_r + 64) * ROWB + ld_c * 16,                  \
                   wlo + (size_t)(n0 + ld_r + 64) * (2 * H_) + kb_ + ld_c * 8);     \
        CP_COMMIT();                                                                \
    } while (0)

    const int total_it = 64;       // 2048 / 32
    FC_ISSUE(0);
    FC_ISSUE(1);

    for (int it = 0; it < total_it; it++) {
        if (it + 2 < total_it) { FC_ISSUE(it + 2); CP_WAIT2(); }
        else if (it + 1 < total_it) { CP_WAIT1(); }
        else { CP_WAIT0(); }
        __syncthreads();

        const uint32_t stg = sb + (it & 3) * STAGE_F;
        #pragma unroll
        for (int ks = 0; ks < 2; ks++) {
            uint32_t Ahi[2][4], Alo[2][4];
            #pragma unroll
            for (int mt = 0; mt < 2; mt++) {
                uint32_t off = (uint32_t)((mw * 32 + mt * 16 + a_l) * ROWB + (ks * 16 + a_kh) * 2);
                ldmx4(Ahi[mt], stg + FC_AHI + off);
                ldmx4(Alo[mt], stg + FC_ALO + off);
            }
            uint32_t Bhi[2][4], Blo[2][4];
            #pragma unroll
            for (int np = 0; np < 2; np++) {
                uint32_t off = (uint32_t)((nw * 32 + np * 16 + b_nb) * ROWB + (ks * 16 + b_kh) * 2);
                ldmx4(Bhi[np], stg + FC_BHI + off);
                ldmx4(Blo[np], stg + FC_BLO + off);
            }
            #pragma unroll
            for (int mt = 0; mt < 2; mt++)
                #pragma unroll
                for (int nt = 0; nt < 4; nt++) {
                    const int np = nt >> 1, pr = (nt & 1) * 2;
                    mma16816(acc[mt][nt], Ahi[mt], Bhi[np][pr], Bhi[np][pr + 1]);
                    mma16816(acc[mt][nt], Ahi[mt], Blo[np][pr], Blo[np][pr + 1]);
                    mma16816(acc[mt][nt], Alo[mt], Bhi[np][pr], Bhi[np][pr + 1]);
                }
        }
        __syncthreads();
    }

    // epilogue: + fcb, store fp32 logits
    #pragma unroll
    for (int nt = 0; nt < 4; nt++) {
        const int col0 = n0 + nw * 32 + nt * 8 + t2;
        const float c0 = __ldg(&fcb[col0]);
        const float c1 = __ldg(&fcb[col0 + 1]);
        #pragma unroll
        for (int mt = 0; mt < 2; mt++) {
            #pragma unroll
            for (int i = 0; i < 2; i++) {
                const int row = mw * 32 + mt * 16 + g + i * 8;
                float2 o;
                o.x = acc[mt][nt][i * 2 + 0] + c0;
                o.y = acc[mt][nt][i * 2 + 1] + c1;
                *reinterpret_cast<float2*>(&logits[(size_t)row * V_ + col0]) = o;
            }
        }
    }
    #undef FC_ISSUE
}

// ---------------- K3: softmax over T, writes attn_w output ----------------
__global__ void softmax_k(const float* __restrict__ scores,
                          float* __restrict__ attn_w_out) {
    int b = blockIdx.x;
    int t = threadIdx.x;
    __shared__ float sh[512];
    float s = scores[t * B_ + b];
    sh[t] = s;
    __syncthreads();
    for (int off = 256; off > 0; off >>= 1) {
        if (t < off) sh[t] = fmaxf(sh[t], sh[t + off]);
        __syncthreads();
    }
    float mx = sh[0];
    __syncthreads();
    float e = expf(s - mx);
    sh[t] = e;
    __syncthreads();
    for (int off = 256; off > 0; off >>= 1) {
        if (t < off) sh[t] += sh[t + off];
        __syncthreads();
    }
    attn_w_out[b * T_ + t] = e / sh[0];
}

// ---------------- K4: context = attn_w @ enc ----------------
__global__ void context_k(const float* __restrict__ enc,
                          const float* __restrict__ attn_w,
                          float* __restrict__ rnn_in,
                          float* __restrict__ cat2) {
    int b = blockIdx.y;
    int h = blockIdx.x * 128 + threadIdx.x;
    __shared__ float w[T_];
    for (int t = threadIdx.x; t < T_; t += 128) w[t] = attn_w[b * T_ + t];
    __syncthreads();
    float acc = 0.f;
    #pragma unroll 4
    for (int t = 0; t < T_; t++)
        acc = fmaf(w[t], enc[(size_t)(t * B_ + b) * H_ + h], acc);
    rnn_in[b * (E_ + H_) + E_ + h] = acc;
    cat2[b * (2 * H_) + H_ + h] = acc;
}

// ---------------- K6: GRU gates (reduces k-split partials inline) ----------------
__global__ void gates_k(const float* __restrict__ pgi,
                        const float* __restrict__ pgh,
                        const float* __restrict__ bih,
                        const float* __restrict__ bhh,
                        const float* __restrict__ lh,
                        float* __restrict__ hnew_out,
                        float* __restrict__ cat2) {
    int b = blockIdx.x;
    for (int h = threadIdx.x; h < H_; h += blockDim.x) {
        float gi0 = bih[h], gi1 = bih[H_ + h], gi2 = bih[2 * H_ + h];
        float gh0 = bhh[h], gh1 = bhh[H_ + h], gh2 = bhh[2 * H_ + h];
        #pragma unroll
        for (int ks = 0; ks < 4; ks++) {
            size_t base = (size_t)((ks << 6) + b) * 3 * H_;
            gi0 += pgi[base + h]; gi1 += pgi[base + H_ + h]; gi2 += pgi[base + 2 * H_ + h];
            gh0 += pgh[base + h]; gh1 += pgh[base + H_ + h]; gh2 += pgh[base + 2 * H_ + h];
        }
        float r = 1.f / (1.f + expf(-(gi0 + gh0)));
        float z = 1.f / (1.f + expf(-(gi1 + gh1)));
        float n = tanhf(gi2 + r * gh2);
        float hp = lh[b * H_ + h];
        float hn = (1.f - z) * n + z * hp;
        hnew_out[b * H_ + h] = hn;
        cat2[b * (2 * H_) + h] = hn;
    }
}

// ---------------- K8: in-place log_softmax on logits rows ----------------
__global__ void logsoftmax_k(float* __restrict__ logits) {
    int b = blockIdx.x;
    int tid = threadIdx.x;
    __shared__ float sh[1024];
    float* row = logits + (size_t)b * V_;
    float mx = -1e30f;
    for (int n = tid; n < V_; n += 1024) mx = fmaxf(mx, row[n]);
    sh[tid] = mx;
    __syncthreads();
    for (int off = 512; off > 0; off >>= 1) {
        if (tid < off) sh[tid] = fmaxf(sh[tid], sh[tid + off]);
        __syncthreads();
    }
    mx = sh[0];
    __syncthreads();
    float sum = 0.f;
    for (int n = tid; n < V_; n += 1024) sum += expf(row[n] - mx);
    sh[tid] = sum;
    __syncthreads();
    for (int off = 512; off > 0; off >>= 1) {
        if (tid < off) sh[tid] += sh[tid + off];
        __syncthreads();
    }
    float lse = mx + logf(sh[0]);
    for (int n = tid; n < V_; n += 1024) row[n] -= lse;
}

// ---------------- launch ----------------
extern "C" void kernel_launch(void* const* d_in, const int* in_sizes, int n_in,
                              void* d_out, int out_size) {
    const int*   x    = (const int*)d_in[0];
    const float* lh   = (const float*)d_in[1];
    const float* enc  = (const float*)d_in[2];
    const float* embW = (const float*)d_in[3];
    const float* attW = (const float*)d_in[4];
    const float* attb = (const float*)d_in[5];
    const float* v    = (const float*)d_in[6];
    const float* Wih  = (const float*)d_in[7];
    const float* Whh  = (const float*)d_in[8];
    const float* bih  = (const float*)d_in[9];
    const float* bhh  = (const float*)d_in[10];
    const float* fcW  = (const float*)d_in[11];
    const float* fcb  = (const float*)d_in[12];

    float* out      = (float*)d_out;
    float* out_logp = out;
    float* out_h    = out + (size_t)B_ * V_;
    float* out_w    = out_h + (size_t)B_ * H_;

    float *rnn_in, *bias_aT, *scoresp, *cat2, *pbias, *pgi, *pgh;
    __nv_bfloat16 *ehi, *elo, *whi, *wlo, *fhi, *flo, *c2hi, *c2lo;
    cudaGetSymbolAddress((void**)&rnn_in,  g_rnn_in);
    cudaGetSymbolAddress((void**)&bias_aT, g_bias_aT);
    cudaGetSymbolAddress((void**)&scoresp, g_scores);
    cudaGetSymbolAddress((void**)&cat2,    g_cat2);
    cudaGetSymbolAddress((void**)&pbias,   g_part_bias);
    cudaGetSymbolAddress((void**)&pgi,     g_part_gi);
    cudaGetSymbolAddress((void**)&pgh,     g_part_gh);
    cudaGetSymbolAddress((void**)&ehi,     g_enc_hi);
    cudaGetSymbolAddress((void**)&elo,     g_enc_lo);
    cudaGetSymbolAddress((void**)&whi,     g_w_hi);
    cudaGetSymbolAddress((void**)&wlo,     g_w_lo);
    cudaGetSymbolAddress((void**)&fhi,     g_fc_hi);
    cudaGetSymbolAddress((void**)&flo,     g_fc_lo);
    cudaGetSymbolAddress((void**)&c2hi,    g_cat2_hi);
    cudaGetSymbolAddress((void**)&c2lo,    g_cat2_lo);

    cudaFuncSetAttribute(energy_mma_k, cudaFuncAttributeMaxDynamicSharedMemorySize, SMEM_ENERGY);
    cudaFuncSetAttribute(fc_mma_k, cudaFuncAttributeMaxDynamicSharedMemorySize, SMEM_FC);

    // bf16 hi/lo splits
    split_flat_k<<<(M_BT * H_ / 4) / 256, 256>>>((const float4*)enc, ehi, elo);
    split_flat_k<<<(int)(((size_t)V_ * 2 * H_ / 4) / 256), 256>>>((const float4*)fcW, fhi, flo);
    split_w_k<<<(H_ * H_ / 4) / 256, 256>>>(attW, whi, wlo);
    // emb gather
    gather_emb_k<<<B_, 128>>>(x, embW, rnn_in);
    // bias_a = attn_b + h @ W1^T  (k-split 8) + reduce/transpose
    gemm_m64_ks<<<dim3(H_ / 64, 8), 256>>>(lh, H_, attW, 2 * H_, pbias, H_, 128);
    bias_redT_k<<<(B_ * H_) / 256, 256>>>(pbias, attb, bias_aT);
    // energy GEMM + fused score reduction
    energy_mma_k<<<M_BT / 128, 256, SMEM_ENERGY>>>(ehi, elo, whi, wlo, bias_aT, v, scoresp);
    // softmax -> attn_w
    softmax_k<<<B_, 512>>>(scoresp, out_w);
    // context
    context_k<<<dim3(H_ / 128, B_), 128>>>(enc, out_w, rnn_in, cat2);
    // GRU projections (k-split 4)
    gemm_m64_ks<<<dim3(3 * H_ / 64, 4), 256>>>(rnn_in, E_ + H_, Wih, E_ + H_, pgi, 3 * H_, 384);
    gemm_m64_ks<<<dim3(3 * H_ / 64, 4), 256>>>(lh, H_, Whh, H_, pgh, 3 * H_, 256);
    // gates (reduces partials) -> h_new + cat2[:, :1024]
    gates_k<<<B_, 256>>>(pgi, pgh, bih, bhh, lh, out_h, cat2);
    // split cat2 to bf16 hi/lo
    split_flat_k<<<(B_ * 2 * H_ / 4) / 256, 256>>>((const float4*)cat2, c2hi, c2lo);
    // fc logits via mma
    fc_mma_k<<<V_ / 128, 256, SMEM_FC>>>(c2hi, c2lo, fhi, flo, fcb, out_logp);
    // log_softmax
    logsoftmax_k<<<B_, 1024>>>(out_logp);
}

// round 7
// speedup vs baseline: 2.1652x; 1.0468x over previous
#include <cuda_runtime.h>
#include <cuda_bf16.h>
#include <math.h>
#include <stdint.h>

#define B_ 64
#define T_ 512
#define H_ 1024
#define E_ 512
#define V_ 32000
#define M_BT (B_ * T_)        // 32768

// ---------------- scratch (device globals; no allocation allowed) ----------------
__device__ float g_rnn_in[B_ * (E_ + H_)];        // [64, 1536]
__device__ float g_bias_aT[H_ * B_];              // [1024, 64]
__device__ float g_scores[M_BT];
__device__ float g_cat2[B_ * 2 * H_];             // [h_new | context]
__device__ float g_part_bias[8 * B_ * H_];
__device__ float g_part_gi[8 * B_ * 3 * H_];
__device__ float g_part_gh[8 * B_ * 3 * H_];
__device__ __nv_bfloat16 g_w_hi[H_ * H_];         // 2 MB
__device__ __nv_bfloat16 g_w_lo[H_ * H_];         // 2 MB

// ======================= helpers =======================
__device__ __forceinline__ uint32_t smem_u32(const void* p) {
    uint32_t a;
    asm("{ .reg .u64 t; cvta.to.shared.u64 t, %1; cvt.u32.u64 %0, t; }" : "=r"(a) : "l"(p));
    return a;
}
#define CP_ASYNC16(dst, src) \
    asm volatile("cp.async.cg.shared.global [%0], [%1], 16;" :: "r"(dst), "l"(src))
#define CP_COMMIT() asm volatile("cp.async.commit_group;" ::: "memory")
#define CP_WAIT2() asm volatile("cp.async.wait_group 2;" ::: "memory")
#define CP_WAIT1() asm volatile("cp.async.wait_group 1;" ::: "memory")
#define CP_WAIT0() asm volatile("cp.async.wait_group 0;" ::: "memory")

__device__ __forceinline__ void ldmx4(uint32_t* r, uint32_t addr) {
    asm volatile("ldmatrix.sync.aligned.m8n8.x4.shared.b16 {%0,%1,%2,%3}, [%4];"
                 : "=r"(r[0]), "=r"(r[1]), "=r"(r[2]), "=r"(r[3]) : "r"(addr));
}
__device__ __forceinline__ void mma16816(float* d, const uint32_t* a, uint32_t b0, uint32_t b1) {
    asm volatile("mma.sync.aligned.m16n8k16.row.col.f32.bf16.bf16.f32 "
                 "{%0,%1,%2,%3}, {%4,%5,%6,%7}, {%8,%9}, {%0,%1,%2,%3};"
                 : "+f"(d[0]), "+f"(d[1]), "+f"(d[2]), "+f"(d[3])
                 : "r"(a[0]), "r"(a[1]), "r"(a[2]), "r"(a[3]), "r"(b0), "r"(b1));
}
// fp32 quad -> bf16 hi/lo quads (8 bytes each)
__device__ __forceinline__ void cvt_hl(float4 x, uint2* hq, uint2* lq) {
    __align__(8) __nv_bfloat16 h[4];
    __align__(8) __nv_bfloat16 l[4];
    float xs[4] = {x.x, x.y, x.z, x.w};
    #pragma unroll
    for (int j = 0; j < 4; j++) {
        h[j] = __float2bfloat16(xs[j]);
        l[j] = __float2bfloat16(xs[j] - __bfloat162float(h[j]));
    }
    *hq = *reinterpret_cast<uint2*>(h);
    *lq = *reinterpret_cast<uint2*>(l);
}

// ======================= tiling constants =======================
#define KSTEP 32
#define ROWB 80
#define TILE_A (128 * ROWB)           // 10240
// energy: B via cp.async (4 stages), A fp32->bf16 inline (2 stages)
#define EN_B_STAGE (2 * TILE_A)       // 20480 (whi|wlo)
#define EN_ABUF_OFF (4 * EN_B_STAGE)  // 81920
#define EN_ABUF_SZ (2 * TILE_A)       // 20480 (ahi|alo)
#define EN_RED_OFF (EN_ABUF_OFF + 2 * EN_ABUF_SZ)   // 122880
#define SMEM_ENERGY (EN_RED_OFF + 512 * 4)          // 124928
// fc: all operands fp32->bf16 inline, 2 stages
#define FC_TA (64 * ROWB)             // 5120
#define FC_TB (128 * ROWB)            // 10240
#define FC_AHI 0
#define FC_ALO FC_TA
#define FC_BHI (2 * FC_TA)
#define FC_BLO (2 * FC_TA + FC_TB)
#define FC_STAGE (2 * FC_TA + 2 * FC_TB)   // 30720
#define SMEM_FC (2 * FC_STAGE)             // 61440

// ---------------- split attn_W[:, H:] -> bf16 hi/lo (2 MB, cheap) ----------------
__global__ void split_w_k(const float* __restrict__ attnW,
                          __nv_bfloat16* __restrict__ hi,
                          __nv_bfloat16* __restrict__ lo) {
    int i = blockIdx.x * blockDim.x + threadIdx.x;   // < H_*H_/4
    int r = i >> 8;
    int k4 = i & 255;
    const float4* src = reinterpret_cast<const float4*>(attnW + (size_t)r * (2 * H_) + H_) + k4;
    uint2 h, l;
    cvt_hl(*src, &h, &l);
    *reinterpret_cast<uint2*>(hi + 4 * (size_t)i) = h;
    *reinterpret_cast<uint2*>(lo + 4 * (size_t)i) = l;
}

// ---------------- K0: embedding gather ----------------
__global__ void gather_emb_k(const int* __restrict__ x,
                             const float* __restrict__ embW,
                             float* __restrict__ rnn_in) {
    int b = blockIdx.x;
    int row = x[b];
    for (int e = threadIdx.x; e < E_; e += blockDim.x)
        rnn_in[b * (E_ + H_) + e] = embW[(size_t)row * E_ + e];
}

// ---------------- K-split M=64 GEMM ----------------
__global__ void gemm_m64_ks(const float* __restrict__ A, int lda,
                            const float* __restrict__ W, int ldw,
                            float* __restrict__ Cp, int ldc, int kc) {
    __shared__ float As[16][64];
    __shared__ float Ws[16][64];
    const int tid = threadIdx.x;
    const int n0 = blockIdx.x * 64;
    const int kk0 = blockIdx.y * kc;
    const int lrow = tid >> 2;
    const int kq = (tid & 3) * 4;
    const int ty = tid >> 4;
    const int tx = tid & 15;

    float acc[4][4] = {};
    for (int kk = kk0; kk < kk0 + kc; kk += 16) {
        float4 av = *(const float4*)&A[lrow * lda + kk + kq];
        float4 wv = *(const float4*)&W[(size_t)(n0 + lrow) * ldw + kk + kq];
        __syncthreads();
        As[kq + 0][lrow] = av.x; As[kq + 1][lrow] = av.y;
        As[kq + 2][lrow] = av.z; As[kq + 3][lrow] = av.w;
        Ws[kq + 0][lrow] = wv.x; Ws[kq + 1][lrow] = wv.y;
        Ws[kq + 2][lrow] = wv.z; Ws[kq + 3][lrow] = wv.w;
        __syncthreads();
        #pragma unroll
        for (int k = 0; k < 16; k++) {
            float4 a = *(const float4*)&As[k][ty * 4];
            float4 w = *(const float4*)&Ws[k][tx * 4];
            float af[4] = {a.x, a.y, a.z, a.w};
            float wf[4] = {w.x, w.y, w.z, w.w};
            #pragma unroll
            for (int i = 0; i < 4; i++)
                #pragma unroll
                for (int j = 0; j < 4; j++)
                    acc[i][j] = fmaf(af[i], wf[j], acc[i][j]);
        }
    }
    #pragma unroll
    for (int i = 0; i < 4; i++) {
        int m = blockIdx.y * 64 + ty * 4 + i;
        #pragma unroll
        for (int j = 0; j < 4; j++)
            Cp[(size_t)m * ldc + n0 + tx * 4 + j] = acc[i][j];
    }
}

// ---------------- bias partial reduce + transpose ----------------
__global__ void bias_redT_k(const float* __restrict__ part,
                            const float* __restrict__ attb,
                            float* __restrict__ biasT) {
    int idx = blockIdx.x * 256 + threadIdx.x;
    int b = idx >> 10, h = idx & 1023;
    float s = attb[h];
    #pragma unroll
    for (int ks = 0; ks < 8; ks++)
        s += part[(size_t)((ks << 6) + b) * H_ + h];
    biasT[h * B_ + b] = s;
}

// ---------------- K2: energy GEMM (enc fp32 converted inline) ----------------
__global__ void __launch_bounds__(256, 1)
energy_mma_k(const float* __restrict__ enc,
             const __nv_bfloat16* __restrict__ whi, const __nv_bfloat16* __restrict__ wlo,
             const float* __restrict__ biasT, const float* __restrict__ v,
             float* __restrict__ scores) {
    extern __shared__ char sm[];
    const uint32_t sb = smem_u32(sm);
    float* red = (float*)(sm + EN_RED_OFF);

    const int tid = threadIdx.x;
    const int wid = tid >> 5;
    const int lane = tid & 31;
    const int m0 = blockIdx.x * 128;
    const int mw = wid >> 2;
    const int nw = wid & 3;

    const int a_l = lane & 15;
    const int a_kh = (lane >> 4) << 3;
    const int b_nb = (lane & 7) + ((lane >> 4) << 3);
    const int b_kh = ((lane >> 3) & 1) << 3;
    const int g = lane >> 2;
    const int t2 = (lane & 3) << 1;

    float acc[4][4][4];
    float rowsum[8];
    #pragma unroll
    for (int i = 0; i < 8; i++) rowsum[i] = 0.f;

    const int total_it = 8 * 32;
    // A (enc fp32) load map: 128 rows x 8 fp32-quads = 1024 chunks, 4 per thread
    const int ar[4] = {tid >> 3, (tid + 256) >> 3, (tid + 512) >> 3, (tid + 768) >> 3};
    const int ac = tid & 7;
    float4 Ar[4];

    #define EN_LDGA(it_) do {                                                       \
        int kb_ = ((it_) & 31) * KSTEP;                                             \
        _Pragma("unroll")                                                           \
        for (int j = 0; j < 4; j++)                                                 \
            Ar[j] = *(const float4*)&enc[(size_t)(m0 + ar[j]) * H_ + kb_ + ac * 4]; \
    } while (0)

    #define EN_STSA(it_) do {                                                       \
        char* ab_ = sm + EN_ABUF_OFF + ((it_) & 1) * EN_ABUF_SZ;                    \
        _Pragma("unroll")                                                           \
        for (int j = 0; j < 4; j++) {                                               \
            uint2 hq_, lq_;                                                         \
            cvt_hl(Ar[j], &hq_, &lq_);                                              \
            *reinterpret_cast<uint2*>(ab_ + ar[j] * ROWB + ac * 8) = hq_;           \
            *reinterpret_cast<uint2*>(ab_ + TILE_A + ar[j] * ROWB + ac * 8) = lq_;  \
        }                                                                           \
    } while (0)

    #define EN_CPB(it_) do {                                                        \
        int chunk_ = (it_) >> 5;                                                    \
        int kb_ = ((it_) & 31) * KSTEP;                                             \
        uint32_t stg_ = sb + ((it_) & 3) * EN_B_STAGE;                              \
        _Pragma("unroll")                                                           \
        for (int j = 0; j < 4; j++) {                                               \
            int id = tid + (j << 8);                                                \
            int tl = id >> 9; int cc = id & 511; int r = cc >> 2; int c = cc & 3;   \
            const __nv_bfloat16* gw = tl ? wlo : whi;                               \
            CP_ASYNC16(stg_ + tl * TILE_A + r * ROWB + c * 16,                      \
                       gw + (size_t)(chunk_ * 128 + r) * H_ + kb_ + c * 8);         \
        }                                                                           \
        CP_COMMIT();                                                                \
    } while (0)

    EN_LDGA(0);
    EN_CPB(0);
    EN_CPB(1);

    for (int it = 0; it < total_it; it++) {
        const int kt = it & 31;
        const int chunk = it >> 5;
        if (kt == 0) {
            #pragma unroll
            for (int mt = 0; mt < 4; mt++)
                #pragma unroll
                for (int nt = 0; nt < 4; nt++)
                    #pragma unroll
                    for (int k = 0; k < 4; k++) acc[mt][nt][k] = 0.f;
        }
        __syncthreads();            // all reads of Abuf[it&1] (iter it-2) + B stage done
        EN_STSA(it);
        if (it + 1 < total_it) EN_LDGA(it + 1);
        if (it + 2 < total_it) { EN_CPB(it + 2); CP_WAIT2(); }
        else if (it + 1 < total_it) { CP_WAIT1(); }
        else { CP_WAIT0(); }
        __syncthreads();            // A STS + B arrival visible to all warps

        const uint32_t aHiB = sb + EN_ABUF_OFF + (it & 1) * EN_ABUF_SZ;
        const uint32_t aLoB = aHiB + TILE_A;
        const uint32_t bHiB = sb + (it & 3) * EN_B_STAGE;
        const uint32_t bLoB = bHiB + TILE_A;

        #pragma unroll
        for (int ks = 0; ks < 2; ks++) {
            uint32_t Ahi[4][4], Alo[4][4];
            #pragma unroll
            for (int mt = 0; mt < 4; mt++) {
                uint32_t off = (uint32_t)((mw * 64 + mt * 16 + a_l) * ROWB + (ks * 16 + a_kh) * 2);
                ldmx4(Ahi[mt], aHiB + off);
                ldmx4(Alo[mt], aLoB + off);
            }
            uint32_t Bhi[2][4], Blo[2][4];
            #pragma unroll
            for (int np = 0; np < 2; np++) {
                uint32_t off = (uint32_t)((nw * 32 + np * 16 + b_nb) * ROWB + (ks * 16 + b_kh) * 2);
                ldmx4(Bhi[np], bHiB + off);
                ldmx4(Blo[np], bLoB + off);
            }
            #pragma unroll
            for (int mt = 0; mt < 4; mt++)
                #pragma unroll
                for (int nt = 0; nt < 4; nt++) {
                    const int np = nt >> 1, pr = (nt & 1) * 2;
                    mma16816(acc[mt][nt], Ahi[mt], Bhi[np][pr], Bhi[np][pr + 1]);
                    mma16816(acc[mt][nt], Ahi[mt], Blo[np][pr], Blo[np][pr + 1]);
                    mma16816(acc[mt][nt], Alo[mt], Bhi[np][pr], Bhi[np][pr + 1]);
                }
        }

        if (kt == 31) {
            #pragma unroll
            for (int nt = 0; nt < 4; nt++) {
                const int col0 = chunk * 128 + nw * 32 + nt * 8 + t2;
                const float v0 = __ldg(&v[col0]);
                const float v1 = __ldg(&v[col0 + 1]);
                #pragma unroll
                for (int mt = 0; mt < 4; mt++) {
                    #pragma unroll
                    for (int i = 0; i < 2; i++) {
                        const int row = mw * 64 + mt * 16 + g + i * 8;
                        const int b = row & (B_ - 1);
                        float e0 = acc[mt][nt][i * 2 + 0] + __ldg(&biasT[(size_t)col0 * B_ + b]);
                        float e1 = acc[mt][nt][i * 2 + 1] + __ldg(&biasT[(size_t)(col0 + 1) * B_ + b]);
                        rowsum[mt * 2 + i] += fmaxf(e0, 0.f) * v0 + fmaxf(e1, 0.f) * v1;
                    }
                }
            }
        }
    }

    #pragma unroll
    for (int k = 0; k < 8; k++) {
        rowsum[k] += __shfl_xor_sync(0xFFFFFFFF, rowsum[k], 1);
        rowsum[k] += __shfl_xor_sync(0xFFFFFFFF, rowsum[k], 2);
    }
    __syncthreads();
    if ((lane & 3) == 0) {
        #pragma unroll
        for (int mt = 0; mt < 4; mt++)
            #pragma unroll
            for (int i = 0; i < 2; i++)
                red[nw * 128 + mw * 64 + mt * 16 + g + i * 8] = rowsum[mt * 2 + i];
    }
    __syncthreads();
    if (tid < 128) {
        float s = red[tid] + red[128 + tid] + red[256 + tid] + red[384 + tid];
        scores[m0 + tid] = s;
    }
    #undef EN_LDGA
    #undef EN_STSA
    #undef EN_CPB
}

// ---------------- fc GEMM (fp32 A and W converted inline) ----------------
__global__ void __launch_bounds__(256, 2)
fc_mma_k(const float* __restrict__ cat2, const float* __restrict__ fcW,
         const float* __restrict__ fcb, float* __restrict__ logits) {
    extern __shared__ char sm[];
    const uint32_t sb = smem_u32(sm);

    const int tid = threadIdx.x;
    const int wid = tid >> 5;
    const int lane = tid & 31;
    const int n0 = blockIdx.x * 128;
    const int mw = wid >> 2;
    const int nw = wid & 3;

    const int a_l = lane & 15;
    const int a_kh = (lane >> 4) << 3;
    const int b_nb = (lane & 7) + ((lane >> 4) << 3);
    const int b_kh = ((lane >> 3) & 1) << 3;
    const int g = lane >> 2;
    const int t2 = (lane & 3) << 1;

    float acc[2][4][4];
    #pragma unroll
    for (int mt = 0; mt < 2; mt++)
        #pragma unroll
        for (int nt = 0; nt < 4; nt++)
            #pragma unroll
            for (int k = 0; k < 4; k++) acc[mt][nt][k] = 0.f;

    // A: 64 rows x 8 quads = 512 chunks (2/thread); B: 128 rows x 8 quads = 1024 (4/thread)
    const int aro[2] = {tid >> 3, (tid + 256) >> 3};
    const int bro[4] = {tid >> 3, (tid + 256) >> 3, (tid + 512) >> 3, (tid + 768) >> 3};
    const int qc = tid & 7;
    float4 Ar[2], Br[4];

    #define FC_LDG(it_) do {                                                        \
        int kb_ = (it_) * KSTEP;                                                    \
        _Pragma("unroll")                                                           \
        for (int j = 0; j < 2; j++)                                                 \
            Ar[j] = *(const float4*)&cat2[(size_t)aro[j] * (2 * H_) + kb_ + qc * 4];\
        _Pragma("unroll")                                                           \
        for (int j = 0; j < 4; j++)                                                 \
            Br[j] = *(const float4*)&fcW[(size_t)(n0 + bro[j]) * (2 * H_) + kb_ + qc * 4]; \
    } while (0)

    #define FC_STS(it_) do {                                                        \
        char* st_ = sm + ((it_) & 1) * FC_STAGE;                                    \
        _Pragma("unroll")                                                           \
        for (int j = 0; j < 2; j++) {                                               \
            uint2 hq_, lq_;                                                         \
            cvt_hl(Ar[j], &hq_, &lq_);                                              \
            *reinterpret_cast<uint2*>(st_ + FC_AHI + aro[j] * ROWB + qc * 8) = hq_; \
            *reinterpret_cast<uint2*>(st_ + FC_ALO + aro[j] * ROWB + qc * 8) = lq_; \
        }                                                                           \
        _Pragma("unroll")                                                           \
        for (int j = 0; j < 4; j++) {                                               \
            uint2 hq_, lq_;                                                         \
            cvt_hl(Br[j], &hq_, &lq_);                                              \
            *reinterpret_cast<uint2*>(st_ + FC_BHI + bro[j] * ROWB + qc * 8) = hq_; \
            *reinterpret_cast<uint2*>(st_ + FC_BLO + bro[j] * ROWB + qc * 8) = lq_; \
        }                                                                           \
    } while (0)

    const int total_it = 64;
    FC_LDG(0);

    for (int it = 0; it < total_it; it++) {
        __syncthreads();
        FC_STS(it);
        if (it + 1 < total_it) FC_LDG(it + 1);
        __syncthreads();

        const uint32_t stg = sb + (it & 1) * FC_STAGE;
        #pragma unroll
        for (int ks = 0; ks < 2; ks++) {
            uint32_t Ahi[2][4], Alo[2][4];
            #pragma unroll
            for (int mt = 0; mt < 2; mt++) {
                uint32_t off = (uint32_t)((mw * 32 + mt * 16 + a_l) * ROWB + (ks * 16 + a_kh) * 2);
                ldmx4(Ahi[mt], stg + FC_AHI + off);
                ldmx4(Alo[mt], stg + FC_ALO + off);
            }
            uint32_t Bhi[2][4], Blo[2][4];
            #pragma unroll
            for (int np = 0; np < 2; np++) {
                uint32_t off = (uint32_t)((nw * 32 + np * 16 + b_nb) * ROWB + (ks * 16 + b_kh) * 2);
                ldmx4(Bhi[np], stg + FC_BHI + off);
                ldmx4(Blo[np], stg + FC_BLO + off);
            }
            #pragma unroll
            for (int mt = 0; mt < 2; mt++)
                #pragma unroll
                for (int nt = 0; nt < 4; nt++) {
                    const int np = nt >> 1, pr = (nt & 1) * 2;
                    mma16816(acc[mt][nt], Ahi[mt], Bhi[np][pr], Bhi[np][pr + 1]);
                    mma16816(acc[mt][nt], Ahi[mt], Blo[np][pr], Blo[np][pr + 1]);
                    mma16816(acc[mt][nt], Alo[mt], Bhi[np][pr], Bhi[np][pr + 1]);
                }
        }
    }

    #pragma unroll
    for (int nt = 0; nt < 4; nt++) {
        const int col0 = n0 + nw * 32 + nt * 8 + t2;
        const float c0 = __ldg(&fcb[col0]);
        const float c1 = __ldg(&fcb[col0 + 1]);
        #pragma unroll
        for (int mt = 0; mt < 2; mt++) {
            #pragma unroll
            for (int i = 0; i < 2; i++) {
                const int row = mw * 32 + mt * 16 + g + i * 8;
                float2 o;
                o.x = acc[mt][nt][i * 2 + 0] + c0;
                o.y = acc[mt][nt][i * 2 + 1] + c1;
                *reinterpret_cast<float2*>(&logits[(size_t)row * V_ + col0]) = o;
            }
        }
    }
    #undef FC_LDG
    #undef FC_STS
}

// ---------------- K3: softmax over T ----------------
__global__ void softmax_k(const float* __restrict__ scores,
                          float* __restrict__ attn_w_out) {
    int b = blockIdx.x;
    int t = threadIdx.x;
    __shared__ float sh[512];
    float s = scores[t * B_ + b];
    sh[t] = s;
    __syncthreads();
    for (int off = 256; off > 0; off >>= 1) {
        if (t < off) sh[t] = fmaxf(sh[t], sh[t + off]);
        __syncthreads();
    }
    float mx = sh[0];
    __syncthreads();
    float e = expf(s - mx);
    sh[t] = e;
    __syncthreads();
    for (int off = 256; off > 0; off >>= 1) {
        if (t < off) sh[t] += sh[t + off];
        __syncthreads();
    }
    attn_w_out[b * T_ + t] = e / sh[0];
}

// ---------------- K4: context = attn_w @ enc (float4) ----------------
__global__ void context_k(const float4* __restrict__ enc4,
                          const float* __restrict__ attn_w,
                          float* __restrict__ rnn_in,
                          float* __restrict__ cat2) {
    int b = blockIdx.y;
    int h4 = blockIdx.x * 128 + threadIdx.x;   // 0..255
    __shared__ float w[T_];
    for (int t = threadIdx.x; t < T_; t += 128) w[t] = attn_w[b * T_ + t];
    __syncthreads();
    float4 acc = {0.f, 0.f, 0.f, 0.f};
    #pragma unroll 4
    for (int t = 0; t < T_; t++) {
        float4 e = enc4[(size_t)(t * B_ + b) * (H_ / 4) + h4];
        float wt = w[t];
        acc.x = fmaf(wt, e.x, acc.x);
        acc.y = fmaf(wt, e.y, acc.y);
        acc.z = fmaf(wt, e.z, acc.z);
        acc.w = fmaf(wt, e.w, acc.w);
    }
    int h = h4 * 4;
    *reinterpret_cast<float4*>(&rnn_in[b * (E_ + H_) + E_ + h]) = acc;
    *reinterpret_cast<float4*>(&cat2[b * (2 * H_) + H_ + h]) = acc;
}

// ---------------- K6: GRU gates (reduce 8 k-split partials) ----------------
__global__ void gates_k(const float* __restrict__ pgi,
                        const float* __restrict__ pgh,
                        const float* __restrict__ bih,
                        const float* __restrict__ bhh,
                        const float* __restrict__ lh,
                        float* __restrict__ hnew_out,
                        float* __restrict__ cat2) {
    int b = blockIdx.x;
    for (int h = threadIdx.x; h < H_; h += blockDim.x) {
        float gi0 = bih[h], gi1 = bih[H_ + h], gi2 = bih[2 * H_ + h];
        float gh0 = bhh[h], gh1 = bhh[H_ + h], gh2 = bhh[2 * H_ + h];
        #pragma unroll
        for (int ks = 0; ks < 8; ks++) {
            size_t base = (size_t)((ks << 6) + b) * 3 * H_;
            gi0 += pgi[base + h]; gi1 += pgi[base + H_ + h]; gi2 += pgi[base + 2 * H_ + h];
            gh0 += pgh[base + h]; gh1 += pgh[base + H_ + h]; gh2 += pgh[base + 2 * H_ + h];
        }
        float r = 1.f / (1.f + expf(-(gi0 + gh0)));
        float z = 1.f / (1.f + expf(-(gi1 + gh1)));
        float n = tanhf(gi2 + r * gh2);
        float hp = lh[b * H_ + h];
        float hn = (1.f - z) * n + z * hp;
        hnew_out[b * H_ + h] = hn;
        cat2[b * (2 * H_) + h] = hn;
    }
}

// ---------------- K8: log_softmax in-place ----------------
__global__ void logsoftmax_k(float* __restrict__ logits) {
    int b = blockIdx.x;
    int tid = threadIdx.x;
    __shared__ float sh[1024];
    float* row = logits + (size_t)b * V_;
    float mx = -1e30f;
    for (int n = tid; n < V_; n += 1024) mx = fmaxf(mx, row[n]);
    sh[tid] = mx;
    __syncthreads();
    for (int off = 512; off > 0; off >>= 1) {
        if (tid < off) sh[tid] = fmaxf(sh[tid], sh[tid + off]);
        __syncthreads();
    }
    mx = sh[0];
    __syncthreads();
    float sum = 0.f;
    for (int n = tid; n < V_; n += 1024) sum += expf(row[n] - mx);
    sh[tid] = sum;
    __syncthreads();
    for (int off = 512; off > 0; off >>= 1) {
        if (tid < off) sh[tid] += sh[tid + off];
        __syncthreads();
    }
    float lse = mx + logf(sh[0]);
    for (int n = tid; n < V_; n += 1024) row[n] -= lse;
}

// ---------------- launch ----------------
extern "C" void kernel_launch(void* const* d_in, const int* in_sizes, int n_in,
                              void* d_out, int out_size) {
    const int*   x    = (const int*)d_in[0];
    const float* lh   = (const float*)d_in[1];
    const float* enc  = (const float*)d_in[2];
    const float* embW = (const float*)d_in[3];
    const float* attW = (const float*)d_in[4];
    const float* attb = (const float*)d_in[5];
    const float* v    = (const float*)d_in[6];
    const float* Wih  = (const float*)d_in[7];
    const float* Whh  = (const float*)d_in[8];
    const float* bih  = (const float*)d_in[9];
    const float* bhh  = (const float*)d_in[10];
    const float* fcW  = (const float*)d_in[11];
    const float* fcb  = (const float*)d_in[12];

    float* out      = (float*)d_out;
    float* out_logp = out;
    float* out_h    = out + (size_t)B_ * V_;
    float* out_w    = out_h + (size_t)B_ * H_;

    float *rnn_in, *bias_aT, *scoresp, *cat2, *pbias, *pgi, *pgh;
    __nv_bfloat16 *whi, *wlo;
    cudaGetSymbolAddress((void**)&rnn_in,  g_rnn_in);
    cudaGetSymbolAddress((void**)&bias_aT, g_bias_aT);
    cudaGetSymbolAddress((void**)&scoresp, g_scores);
    cudaGetSymbolAddress((void**)&cat2,    g_cat2);
    cudaGetSymbolAddress((void**)&pbias,   g_part_bias);
    cudaGetSymbolAddress((void**)&pgi,     g_part_gi);
    cudaGetSymbolAddress((void**)&pgh,     g_part_gh);
    cudaGetSymbolAddress((void**)&whi,     g_w_hi);
    cudaGetSymbolAddress((void**)&wlo,     g_w_lo);

    cudaFuncSetAttribute(energy_mma_k, cudaFuncAttributeMaxDynamicSharedMemorySize, SMEM_ENERGY);
    cudaFuncSetAttribute(fc_mma_k, cudaFuncAttributeMaxDynamicSharedMemorySize, SMEM_FC);

    // attn_W split (2 MB, reused 256x by energy kernel)
    split_w_k<<<(H_ * H_ / 4) / 256, 256>>>(attW, whi, wlo);
    // emb gather
    gather_emb_k<<<B_, 128>>>(x, embW, rnn_in);
    // bias_a (k-split 8) + reduce/transpose
    gemm_m64_ks<<<dim3(H_ / 64, 8), 256>>>(lh, H_, attW, 2 * H_, pbias, H_, 128);
    bias_redT_k<<<(B_ * H_) / 256, 256>>>(pbias, attb, bias_aT);
    // energy GEMM (inline enc conversion) + fused score reduction
    energy_mma_k<<<M_BT / 128, 256, SMEM_ENERGY>>>(enc, whi, wlo, bias_aT, v, scoresp);
    // softmax -> attn_w
    softmax_k<<<B_, 512>>>(scoresp, out_w);
    // context (float4)
    context_k<<<dim3(2, B_), 128>>>((const float4*)enc, out_w, rnn_in, cat2);
    // GRU projections (k-split 8)
    gemm_m64_ks<<<dim3(3 * H_ / 64, 8), 256>>>(rnn_in, E_ + H_, Wih, E_ + H_, pgi, 3 * H_, 192);
    gemm_m64_ks<<<dim3(3 * H_ / 64, 8), 256>>>(lh, H_, Whh, H_, pgh, 3 * H_, 128);
    // gates -> h_new + cat2[:, :1024]
    gates_k<<<B_, 256>>>(pgi, pgh, bih, bhh, lh, out_h, cat2);
    // fc logits (inline fp32 conversion)
    fc_mma_k<<<V_ / 128, 256, SMEM_FC>>>(cat2, fcW, fcb, out_logp);
    // log_softmax
    logsoftmax_k<<<B_, 1024>>>(out_logp);
}